// round 1
// baseline (speedup 1.0000x reference)
#include <cuda_runtime.h>
#include <cstdint>

#define NN 2048
#define TT 16
#define DD 16
#define HH 64
#define NP (NN*NN)        // 4194304 pairs
#define NP2 (NP/2)        // 2097152 pair-pairs (512B each)

// ---------------- device scratch (static, no allocation) ----------------
__device__ __align__(16) float g_S0[NP];          // 16 MB: leaky(rel.w1+b1)+mask
__device__ __align__(16) float g_emb[NN*HH];      // LSTM last hidden
__device__ __align__(16) float g_rowadd[NN];      // leaky(emb.w2+b2)+leaky(emb.w3+b3)
__device__ __align__(16) float g_M[NN];           // column max
__device__ __align__(16) float g_iZ[NN];          // 1/column sumexp
__device__ __align__(16) float g_part[16*NN*HH];  // 8 MB partial outputs (16 j-chunks)

__device__ __forceinline__ float sigm(float v) {
    v = fminf(fmaxf(v, -30.f), 30.f);
    return __fdividef(1.f, 1.f + __expf(-v));
}
__device__ __forceinline__ float tanhx(float v) {
    v = fminf(fmaxf(v, -30.f), 30.f);
    float e = __expf(-2.f * v);
    return __fdividef(1.f - e, 1.f + e);
}
__device__ __forceinline__ float leaky(float v) { return fmaxf(0.2f * v, v); }

// ---------------- K1: fused LSTM (warps 0-7) + relation reduce (warps 8-19) ----
#define K1_BLOCKS 148
#define LSTM_BLOCKS 128
#define K1_THREADS 640
#define RELW_PB 12
#define NRELW (K1_BLOCKS*RELW_PB + (K1_BLOCKS-LSTM_BLOCKS)*8)   // 1936
#define RU 12

// smem float offsets
#define SM_WHH 0          // 64*64*4 = 16384  (layout [(k*64+j)*4 + gate])
#define SM_WIH 16384      // 16*64*4 = 4096   (layout [(d*64+j)*4 + gate])
#define SM_X   20480      // 16 rows * 256
#define SM_H   24576      // 2 * 16 * 64
#define SM_TOT 26624      // floats -> 106496 bytes

__global__ __launch_bounds__(K1_THREADS, 1)
void k1_lstm_rel(const float* __restrict__ x, const float* __restrict__ rel,
                 const float* __restrict__ mask,
                 const float* __restrict__ Wih, const float* __restrict__ Whh,
                 const float* __restrict__ bih, const float* __restrict__ bhh,
                 const float* __restrict__ w1, const float* __restrict__ b1p)
{
    extern __shared__ float sm[];
    const int tid = threadIdx.x;
    const int w = tid >> 5;
    const int bx = blockIdx.x;

    if (bx < LSTM_BLOCKS && w < 8) {
        // ---------------- LSTM role: 256 threads, 16 rows ----------------
        const int j  = tid & 63;        // hidden index
        const int rg = tid >> 6;        // row group 0..3 (4 rows each)
        const int r0 = rg * 4;
        const int row0 = bx * 16;

        float* Whh_P = sm + SM_WHH;
        float* Wih_P = sm + SM_WIH;
        float* x_s   = sm + SM_X;
        float* h_s   = sm + SM_H;

        for (int idx = tid; idx < 16384; idx += 256) {
            int gr = idx >> 6, k = idx & 63;
            int gate = gr >> 6, jj = gr & 63;
            Whh_P[((k << 6) + jj) * 4 + gate] = Whh[idx];
        }
        for (int idx = tid; idx < 4096; idx += 256) {
            int gr = idx >> 4, d = idx & 15;
            int gate = gr >> 6, jj = gr & 63;
            Wih_P[((d << 6) + jj) * 4 + gate] = Wih[idx];
        }
        for (int idx = tid; idx < 16 * TT * DD; idx += 256)
            x_s[idx] = x[(size_t)row0 * TT * DD + idx];
        for (int idx = tid; idx < 2048; idx += 256) h_s[idx] = 0.f;

        float bias_i = bih[j]       + bhh[j];
        float bias_f = bih[64 + j]  + bhh[64 + j];
        float bias_g = bih[128 + j] + bhh[128 + j];
        float bias_o = bih[192 + j] + bhh[192 + j];

        float c[4] = {0.f, 0.f, 0.f, 0.f};
        asm volatile("bar.sync 1, 256;" ::: "memory");

        int buf = 0;
        for (int t = 0; t < TT; t++) {
            float4 a[4];
            #pragma unroll
            for (int q = 0; q < 4; q++) {
                a[q].x = bias_i; a[q].y = bias_f; a[q].z = bias_g; a[q].w = bias_o;
            }
            // input projection: x[row][t][:] . Wih
            const float* xb = x_s + t * DD;
            #pragma unroll
            for (int d = 0; d < DD; d++) {
                float4 wi = *(const float4*)(Wih_P + (((d << 6) + j) << 2));
                #pragma unroll
                for (int q = 0; q < 4; q++) {
                    float xv = xb[(r0 + q) * 256 + d];
                    a[q].x = fmaf(wi.x, xv, a[q].x);
                    a[q].y = fmaf(wi.y, xv, a[q].y);
                    a[q].z = fmaf(wi.z, xv, a[q].z);
                    a[q].w = fmaf(wi.w, xv, a[q].w);
                }
            }
            // recurrent: h . Whh
            const float* hb = h_s + buf * 1024;
            #pragma unroll 8
            for (int k = 0; k < HH; k++) {
                float4 wh = *(const float4*)(Whh_P + (((k << 6) + j) << 2));
                #pragma unroll
                for (int q = 0; q < 4; q++) {
                    float hv = hb[(r0 + q) * 64 + k];
                    a[q].x = fmaf(wh.x, hv, a[q].x);
                    a[q].y = fmaf(wh.y, hv, a[q].y);
                    a[q].z = fmaf(wh.z, hv, a[q].z);
                    a[q].w = fmaf(wh.w, hv, a[q].w);
                }
            }
            float* hn = h_s + (buf ^ 1) * 1024;
            #pragma unroll
            for (int q = 0; q < 4; q++) {
                float ig = sigm(a[q].x);
                float fg = sigm(a[q].y);
                float gg = tanhx(a[q].z);
                float og = sigm(a[q].w);
                c[q] = fmaf(fg, c[q], ig * gg);
                float hv = og * tanhx(c[q]);
                hn[(r0 + q) * 64 + j] = hv;
                if (t == TT - 1) g_emb[(size_t)(row0 + r0 + q) * 64 + j] = hv;
            }
            asm volatile("bar.sync 1, 256;" ::: "memory");
            buf ^= 1;
        }
    } else if (w >= 8 || bx >= LSTM_BLOCKS) {
        // ---------------- relation role ----------------
        int rw;
        if (w >= 8) rw = bx * RELW_PB + (w - 8);
        else        rw = K1_BLOCKS * RELW_PB + (bx - LSTM_BLOCKS) * 8 + w;

        const int lane = tid & 31;
        const int sub  = lane & 15;
        const int half = lane >> 4;
        float4 w1v = *(const float4*)(w1 + sub * 4);
        float b1v = __ldg(b1p);
        const float4* rel4 = (const float4*)rel;

        for (long base = (long)rw * RU; base < NP2; base += (long)NRELW * RU) {
            float4 v[RU];
            #pragma unroll
            for (int k = 0; k < RU; k++) {
                long p2 = base + k;
                if (p2 < NP2) v[k] = __ldcs(rel4 + p2 * 32 + lane);
            }
            #pragma unroll
            for (int k = 0; k < RU; k++) {
                long p2 = base + k;
                if (p2 < NP2) {
                    float s = v[k].x * w1v.x + v[k].y * w1v.y
                            + v[k].z * w1v.z + v[k].w * w1v.w;
                    s += __shfl_down_sync(0xffffffffu, s, 8, 16);
                    s += __shfl_down_sync(0xffffffffu, s, 4, 16);
                    s += __shfl_down_sync(0xffffffffu, s, 2, 16);
                    s += __shfl_down_sync(0xffffffffu, s, 1, 16);
                    if (sub == 0) {
                        long p = 2 * p2 + half;
                        float vv = leaky(s + b1v);
                        g_S0[p] = vv + __ldcs(mask + p);
                    }
                }
            }
        }
    }
}

// ---------------- K2: rowadd[i] = leaky(emb.w2+b2)+leaky(emb.w3+b3) ----------
__global__ void k2_rowadd(const float* __restrict__ w2, const float* __restrict__ b2,
                          const float* __restrict__ w3, const float* __restrict__ b3)
{
    __shared__ float w2_s[64], w3_s[64];
    int tid = threadIdx.x;
    if (tid < 64) { w2_s[tid] = w2[tid]; w3_s[tid] = w3[tid]; }
    __syncthreads();
    int i = blockIdx.x * 256 + tid;
    const float4* e4 = (const float4*)(g_emb + (size_t)i * 64);
    float s2 = 0.f, s3 = 0.f;
    #pragma unroll
    for (int k = 0; k < 16; k++) {
        float4 e = e4[k];
        float4 a = ((const float4*)w2_s)[k];
        float4 b = ((const float4*)w3_s)[k];
        s2 += e.x*a.x + e.y*a.y + e.z*a.z + e.w*a.w;
        s3 += e.x*b.x + e.y*b.y + e.z*b.z + e.w*b.w;
    }
    s2 += __ldg(b2); s3 += __ldg(b3);
    g_rowadd[i] = leaky(s2) + leaky(s3);
}

// ---------------- K3: per-column online max / sumexp -------------------------
__global__ void k3_stats()
{
    int tid = threadIdx.x;
    int jb = blockIdx.x * 16;
    __shared__ float ra_s[NN];
    for (int idx = tid; idx < NN; idx += 256) ra_s[idx] = g_rowadd[idx];
    __syncthreads();
    int c = tid & 15, rs = tid >> 4;          // 16 cols x 16 row-strides
    float m = -1e30f, s = 0.f;
    for (int rb = rs; rb < NN; rb += 128) {
        float vv[8];
        #pragma unroll
        for (int u = 0; u < 8; u++) {
            int r = rb + u * 16;
            vv[u] = g_S0[(size_t)r * NN + jb + c] + ra_s[r];
        }
        #pragma unroll
        for (int u = 0; u < 8; u++) {
            float v = vv[u];
            if (v <= m) s += __expf(v - m);
            else { s = s * __expf(m - v) + 1.f; m = v; }
        }
    }
    __shared__ float ms[256], ss[256];
    ms[tid] = m; ss[tid] = s;
    __syncthreads();
    if (tid < 16) {
        float M = ms[tid], S = ss[tid];
        #pragma unroll
        for (int k = 1; k < 16; k++) {
            float m2 = ms[k * 16 + tid], s2 = ss[k * 16 + tid];
            if (m2 <= M) S += s2 * __expf(m2 - M);
            else { S = S * __expf(M - m2) + s2; M = m2; }
        }
        g_M[jb + tid] = M;
        g_iZ[jb + tid] = __fdividef(1.f, S);
    }
}

// ---------------- K4: out_partial = softmax(S0+rowadd) @ emb -----------------
__global__ __launch_bounds__(128) void k4_prop()
{
    int tid = threadIdx.x;
    int i  = blockIdx.x * 128 + tid;
    int j0 = blockIdx.y * 128;
    __shared__ float emb_s[128 * 64];
    __shared__ float M_s[128], iZ_s[128];
    for (int idx = tid; idx < 128 * 64; idx += 128) emb_s[idx] = g_emb[(size_t)j0 * 64 + idx];
    M_s[tid] = g_M[j0 + tid];
    iZ_s[tid] = g_iZ[j0 + tid];
    float ra = __ldg(g_rowadd + i);
    __syncthreads();

    float4 acc[16];
    #pragma unroll
    for (int k = 0; k < 16; k++) acc[k] = make_float4(0.f, 0.f, 0.f, 0.f);

    const float4* s4 = (const float4*)(g_S0 + (size_t)i * NN + j0);
    for (int jj = 0; jj < 128; jj += 4) {
        float4 sv = __ldg(s4 + (jj >> 2));
        float svv[4] = {sv.x, sv.y, sv.z, sv.w};
        #pragma unroll
        for (int u = 0; u < 4; u++) {
            float p = __expf(svv[u] + ra - M_s[jj + u]) * iZ_s[jj + u];
            const float4* e4 = (const float4*)(emb_s + (jj + u) * 64);
            #pragma unroll
            for (int k = 0; k < 16; k++) {
                float4 e = e4[k];
                acc[k].x = fmaf(p, e.x, acc[k].x);
                acc[k].y = fmaf(p, e.y, acc[k].y);
                acc[k].z = fmaf(p, e.z, acc[k].z);
                acc[k].w = fmaf(p, e.w, acc[k].w);
            }
        }
    }
    float4* dst = (float4*)(g_part + ((size_t)blockIdx.y * NN + i) * HH);
    #pragma unroll
    for (int k = 0; k < 16; k++) dst[k] = acc[k];
}

// ---------------- K5: reduce partials + final prediction ---------------------
__global__ void k5_final(const float* __restrict__ w4, const float* __restrict__ b4,
                         float* __restrict__ out)
{
    __shared__ float w4_s[128];
    int tid = threadIdx.x;
    if (tid < 128) w4_s[tid] = w4[tid];
    __syncthreads();
    int i = blockIdx.x * 256 + tid;
    float pred = __ldg(b4);
    const float4* e4 = (const float4*)(g_emb + (size_t)i * 64);
    #pragma unroll
    for (int k = 0; k < 16; k++) {
        float4 e = e4[k];
        float4 wv = ((const float4*)w4_s)[k];
        pred += e.x*wv.x + e.y*wv.y + e.z*wv.z + e.w*wv.w;
    }
    #pragma unroll
    for (int k = 0; k < 16; k++) {
        float4 o = make_float4(0.f, 0.f, 0.f, 0.f);
        #pragma unroll
        for (int cc = 0; cc < 16; cc++) {
            const float4* p4 = (const float4*)(g_part + ((size_t)cc * NN + i) * HH);
            float4 v = p4[k];
            o.x += v.x; o.y += v.y; o.z += v.z; o.w += v.w;
        }
        float4 wv = ((const float4*)w4_s)[16 + k];
        pred += o.x*wv.x + o.y*wv.y + o.z*wv.z + o.w*wv.w;
    }
    out[i] = leaky(pred);
}

// ---------------- launch ------------------------------------------------------
extern "C" void kernel_launch(void* const* d_in, const int* in_sizes, int n_in,
                              void* d_out, int out_size)
{
    const float* x    = (const float*)d_in[0];
    const float* rel  = (const float*)d_in[1];
    const float* mask = (const float*)d_in[2];
    const float* Wih  = (const float*)d_in[3];
    const float* Whh  = (const float*)d_in[4];
    const float* bih  = (const float*)d_in[5];
    const float* bhh  = (const float*)d_in[6];
    const float* w1   = (const float*)d_in[7];
    const float* b1   = (const float*)d_in[8];
    const float* w2   = (const float*)d_in[9];
    const float* b2   = (const float*)d_in[10];
    const float* w3   = (const float*)d_in[11];
    const float* b3   = (const float*)d_in[12];
    const float* w4   = (const float*)d_in[13];
    const float* b4   = (const float*)d_in[14];

    static_assert(SM_TOT * 4 == 106496, "smem layout");
    cudaFuncSetAttribute(k1_lstm_rel, cudaFuncAttributeMaxDynamicSharedMemorySize,
                         SM_TOT * (int)sizeof(float));

    k1_lstm_rel<<<K1_BLOCKS, K1_THREADS, SM_TOT * sizeof(float)>>>(
        x, rel, mask, Wih, Whh, bih, bhh, w1, b1);
    k2_rowadd<<<NN / 256, 256>>>(w2, b2, w3, b3);
    k3_stats<<<NN / 16, 256>>>();
    k4_prop<<<dim3(NN / 128, NN / 128), 128>>>();
    k5_final<<<NN / 256, 256>>>(w4, b4, (float*)d_out);
}

// round 2
// speedup vs baseline: 1.2718x; 1.2718x over previous
#include <cuda_runtime.h>
#include <cstdint>

#define NN 2048
#define TT 16
#define DD 16
#define HH 64
#define NP (NN*NN)        // 4194304 pairs
#define NP2 (NP/2)        // 2097152 pair-pairs (512B each)

// ---------------- device scratch (static, no allocation) ----------------
__device__ __align__(16) float g_E0[NP];          // 16 MB: exp(leaky(rel.w1+b1)+mask)
__device__ __align__(16) float g_emb[NN*HH];      // LSTM last hidden
__device__ __align__(16) float g_era[NN];         // exp(leaky(emb.w2+b2)+leaky(emb.w3+b3))
__device__ __align__(16) float g_zpart[16*NN];    // column-sum partials
__device__ __align__(16) float g_iZ[NN];          // 1/column sumexp
__device__ __align__(16) float g_part[16*NN*HH];  // 8 MB partial outputs (16 j-chunks)

__device__ __forceinline__ float sigm(float v) {
    v = fminf(fmaxf(v, -30.f), 30.f);
    return __fdividef(1.f, 1.f + __expf(-v));
}
__device__ __forceinline__ float tanhx(float v) {
    v = fminf(fmaxf(v, -30.f), 30.f);
    float e = __expf(-2.f * v);
    return __fdividef(1.f - e, 1.f + e);
}
__device__ __forceinline__ float leaky(float v) { return fmaxf(0.2f * v, v); }

// ---------------- K1: fused LSTM (warps 0-7) + relation reduce ---------------
#define K1_BLOCKS 148
#define LSTM_BLOCKS 128
#define K1_THREADS 640
#define RELW_PB 12
#define NRELW (K1_BLOCKS*RELW_PB + (K1_BLOCKS-LSTM_BLOCKS)*8)   // 1936 distinct rel warps

// smem float offsets
#define SM_WHH 0          // 64*64*4 floats (layout [(k*64+j)*4 + gate])
#define SM_WIH 16384      // 16*64*4
#define SM_X   20480      // 16 rows * 256
#define SM_H   24576      // 2 * 16 * 64
#define SM_TOT 26624      // floats -> 106496 bytes

// process one batch of 16 pair-pairs (32 pairs = 8KB of rel)
__device__ __forceinline__ void rel_batch(
    const float4* __restrict__ rel4, const float* __restrict__ mask,
    long base, int lane, float4 w1v, float b1v, bool guard)
{
    float myS = 0.f;
    #pragma unroll
    for (int half = 0; half < 2; half++) {
        float4 v[8];
        #pragma unroll
        for (int k = 0; k < 8; k++) {
            long p2 = base + half * 8 + k;
            if (!guard || p2 < NP2) v[k] = __ldcs(rel4 + p2 * 32 + lane);
            else v[k] = make_float4(0.f, 0.f, 0.f, 0.f);
        }
        #pragma unroll
        for (int k = 0; k < 8; k++) {
            float s = v[k].x * w1v.x + v[k].y * w1v.y
                    + v[k].z * w1v.z + v[k].w * w1v.w;
            s += __shfl_xor_sync(0xffffffffu, s, 8, 16);
            s += __shfl_xor_sync(0xffffffffu, s, 4, 16);
            s += __shfl_xor_sync(0xffffffffu, s, 2, 16);
            s += __shfl_xor_sync(0xffffffffu, s, 1, 16);
            // pair 2k+h result lives in half h (lanes h*16..h*16+15)
            float got = __shfl_sync(0xffffffffu, s, (lane & 1) << 4);
            int kk = half * 8 + k;
            if ((lane >> 1) == kk) myS = got;
        }
    }
    long p = 2 * base + lane;   // this lane's pair index
    if (!guard || p < NP) {
        float mk = __ldcs(mask + p);
        g_E0[p] = __expf(leaky(myS + b1v) + mk);
    }
}

__global__ __launch_bounds__(K1_THREADS, 1)
void k1_lstm_rel(const float* __restrict__ x, const float* __restrict__ rel,
                 const float* __restrict__ mask,
                 const float* __restrict__ Wih, const float* __restrict__ Whh,
                 const float* __restrict__ bih, const float* __restrict__ bhh,
                 const float* __restrict__ w1, const float* __restrict__ b1p)
{
    extern __shared__ float sm[];
    const int tid = threadIdx.x;
    const int w = tid >> 5;
    const int bx = blockIdx.x;

    if (bx < LSTM_BLOCKS && w < 8) {
        // ---------------- LSTM role: 256 threads, 16 rows ----------------
        const int j  = tid & 63;
        const int rg = tid >> 6;
        const int r0 = rg * 4;
        const int row0 = bx * 16;

        float* Whh_P = sm + SM_WHH;
        float* Wih_P = sm + SM_WIH;
        float* x_s   = sm + SM_X;
        float* h_s   = sm + SM_H;

        for (int idx = tid; idx < 16384; idx += 256) {
            int gr = idx >> 6, k = idx & 63;
            int gate = gr >> 6, jj = gr & 63;
            Whh_P[((k << 6) + jj) * 4 + gate] = Whh[idx];
        }
        for (int idx = tid; idx < 4096; idx += 256) {
            int gr = idx >> 4, d = idx & 15;
            int gate = gr >> 6, jj = gr & 63;
            Wih_P[((d << 6) + jj) * 4 + gate] = Wih[idx];
        }
        for (int idx = tid; idx < 16 * TT * DD; idx += 256)
            x_s[idx] = x[(size_t)row0 * TT * DD + idx];
        for (int idx = tid; idx < 2048; idx += 256) h_s[idx] = 0.f;

        float bias_i = bih[j]       + bhh[j];
        float bias_f = bih[64 + j]  + bhh[64 + j];
        float bias_g = bih[128 + j] + bhh[128 + j];
        float bias_o = bih[192 + j] + bhh[192 + j];

        float c[4] = {0.f, 0.f, 0.f, 0.f};
        asm volatile("bar.sync 1, 256;" ::: "memory");

        int buf = 0;
        for (int t = 0; t < TT; t++) {
            float4 a[4];
            #pragma unroll
            for (int q = 0; q < 4; q++) {
                a[q].x = bias_i; a[q].y = bias_f; a[q].z = bias_g; a[q].w = bias_o;
            }
            const float* xb = x_s + t * DD;
            #pragma unroll
            for (int d = 0; d < DD; d++) {
                float4 wi = *(const float4*)(Wih_P + (((d << 6) + j) << 2));
                #pragma unroll
                for (int q = 0; q < 4; q++) {
                    float xv = xb[(r0 + q) * 256 + d];
                    a[q].x = fmaf(wi.x, xv, a[q].x);
                    a[q].y = fmaf(wi.y, xv, a[q].y);
                    a[q].z = fmaf(wi.z, xv, a[q].z);
                    a[q].w = fmaf(wi.w, xv, a[q].w);
                }
            }
            const float* hb = h_s + buf * 1024;
            #pragma unroll 8
            for (int k = 0; k < HH; k++) {
                float4 wh = *(const float4*)(Whh_P + (((k << 6) + j) << 2));
                #pragma unroll
                for (int q = 0; q < 4; q++) {
                    float hv = hb[(r0 + q) * 64 + k];
                    a[q].x = fmaf(wh.x, hv, a[q].x);
                    a[q].y = fmaf(wh.y, hv, a[q].y);
                    a[q].z = fmaf(wh.z, hv, a[q].z);
                    a[q].w = fmaf(wh.w, hv, a[q].w);
                }
            }
            float* hn = h_s + (buf ^ 1) * 1024;
            #pragma unroll
            for (int q = 0; q < 4; q++) {
                float ig = sigm(a[q].x);
                float fg = sigm(a[q].y);
                float gg = tanhx(a[q].z);
                float og = sigm(a[q].w);
                c[q] = fmaf(fg, c[q], ig * gg);
                float hv = og * tanhx(c[q]);
                hn[(r0 + q) * 64 + j] = hv;
                if (t == TT - 1) g_emb[(size_t)(row0 + r0 + q) * 64 + j] = hv;
            }
            asm volatile("bar.sync 1, 256;" ::: "memory");
            buf ^= 1;
        }
    } else {
        // ---------------- relation role ----------------
        int rw;
        if (w >= 8) rw = bx * RELW_PB + (w - 8);
        else        rw = K1_BLOCKS * RELW_PB + (bx - LSTM_BLOCKS) * 8 + w;

        const int lane = tid & 31;
        const int sub  = lane & 15;
        float4 w1v = *(const float4*)(w1 + sub * 4);
        float b1v = __ldg(b1p);
        const float4* rel4 = (const float4*)rel;

        const long stride = (long)NRELW * 16;
        long base = (long)rw * 16;
        for (; base + 16 <= NP2; base += stride)
            rel_batch(rel4, mask, base, lane, w1v, b1v, false);
        if (base < NP2)
            rel_batch(rel4, mask, base, lane, w1v, b1v, true);
    }
}

// ---------------- K2: era[i] = exp(leaky(emb.w2+b2)+leaky(emb.w3+b3)) --------
__global__ void k2_rowexp(const float* __restrict__ w2, const float* __restrict__ b2,
                          const float* __restrict__ w3, const float* __restrict__ b3)
{
    __shared__ float w2_s[64], w3_s[64];
    int tid = threadIdx.x;
    if (tid < 64) { w2_s[tid] = w2[tid]; w3_s[tid] = w3[tid]; }
    __syncthreads();
    int i = blockIdx.x * 256 + tid;
    const float4* e4 = (const float4*)(g_emb + (size_t)i * 64);
    float s2 = 0.f, s3 = 0.f;
    #pragma unroll
    for (int k = 0; k < 16; k++) {
        float4 e = e4[k];
        float4 a = ((const float4*)w2_s)[k];
        float4 b = ((const float4*)w3_s)[k];
        s2 += e.x*a.x + e.y*a.y + e.z*a.z + e.w*a.w;
        s3 += e.x*b.x + e.y*b.y + e.z*b.z + e.w*b.w;
    }
    s2 += __ldg(b2); s3 += __ldg(b3);
    g_era[i] = __expf(leaky(s2) + leaky(s3));
}

// ---------------- K2b: zpart[by][j] = sum over 128-row chunk of era[i]*E0[i,j]
__global__ __launch_bounds__(256) void k2b_colsum()
{
    __shared__ float era_s[128];
    int tid = threadIdx.x;
    int j = blockIdx.x * 256 + tid;
    int i0 = blockIdx.y * 128;
    if (tid < 128) era_s[tid] = g_era[i0 + tid];
    __syncthreads();
    float acc = 0.f;
    #pragma unroll 8
    for (int r = 0; r < 128; r++)
        acc = fmaf(era_s[r], g_E0[(size_t)(i0 + r) * NN + j], acc);
    g_zpart[blockIdx.y * NN + j] = acc;
}

// ---------------- K2c: iZ[j] = 1 / sum_c zpart[c][j] -------------------------
__global__ void k2c_invz()
{
    int j = blockIdx.x * 256 + threadIdx.x;
    float s = 0.f;
    #pragma unroll
    for (int c = 0; c < 16; c++) s += g_zpart[c * NN + j];
    g_iZ[j] = __fdividef(1.f, s);
}

// ---------------- K4: out_partial = P @ emb  (exp-free) ----------------------
__global__ __launch_bounds__(128) void k4_prop()
{
    int tid = threadIdx.x;
    int i  = blockIdx.x * 128 + tid;
    int j0 = blockIdx.y * 128;
    __shared__ float emb_s[128 * 64];
    __shared__ float iZ_s[128];
    for (int idx = tid; idx < 128 * 64; idx += 128) emb_s[idx] = g_emb[(size_t)j0 * 64 + idx];
    iZ_s[tid] = g_iZ[j0 + tid];
    float eri = __ldg(g_era + i);
    __syncthreads();

    float4 acc[16];
    #pragma unroll
    for (int k = 0; k < 16; k++) acc[k] = make_float4(0.f, 0.f, 0.f, 0.f);

    const float4* s4 = (const float4*)(g_E0 + (size_t)i * NN + j0);
    for (int jj = 0; jj < 128; jj += 4) {
        float4 ev = __ldg(s4 + (jj >> 2));
        float evv[4] = {ev.x, ev.y, ev.z, ev.w};
        #pragma unroll
        for (int u = 0; u < 4; u++) {
            float p = evv[u] * eri * iZ_s[jj + u];
            const float4* e4 = (const float4*)(emb_s + (jj + u) * 64);
            #pragma unroll
            for (int k = 0; k < 16; k++) {
                float4 e = e4[k];
                acc[k].x = fmaf(p, e.x, acc[k].x);
                acc[k].y = fmaf(p, e.y, acc[k].y);
                acc[k].z = fmaf(p, e.z, acc[k].z);
                acc[k].w = fmaf(p, e.w, acc[k].w);
            }
        }
    }
    float4* dst = (float4*)(g_part + ((size_t)blockIdx.y * NN + i) * HH);
    #pragma unroll
    for (int k = 0; k < 16; k++) dst[k] = acc[k];
}

// ---------------- K5: reduce partials + final prediction ---------------------
__global__ void k5_final(const float* __restrict__ w4, const float* __restrict__ b4,
                         float* __restrict__ out)
{
    __shared__ float w4_s[128];
    int tid = threadIdx.x;
    if (tid < 128) w4_s[tid] = w4[tid];
    __syncthreads();
    int i = blockIdx.x * 256 + tid;
    float pred = __ldg(b4);
    const float4* e4 = (const float4*)(g_emb + (size_t)i * 64);
    #pragma unroll
    for (int k = 0; k < 16; k++) {
        float4 e = e4[k];
        float4 wv = ((const float4*)w4_s)[k];
        pred += e.x*wv.x + e.y*wv.y + e.z*wv.z + e.w*wv.w;
    }
    #pragma unroll
    for (int k = 0; k < 16; k++) {
        float4 o = make_float4(0.f, 0.f, 0.f, 0.f);
        #pragma unroll
        for (int cc = 0; cc < 16; cc++) {
            const float4* p4 = (const float4*)(g_part + ((size_t)cc * NN + i) * HH);
            float4 v = p4[k];
            o.x += v.x; o.y += v.y; o.z += v.z; o.w += v.w;
        }
        float4 wv = ((const float4*)w4_s)[16 + k];
        pred += o.x*wv.x + o.y*wv.y + o.z*wv.z + o.w*wv.w;
    }
    out[i] = leaky(pred);
}

// ---------------- launch ------------------------------------------------------
extern "C" void kernel_launch(void* const* d_in, const int* in_sizes, int n_in,
                              void* d_out, int out_size)
{
    const float* x    = (const float*)d_in[0];
    const float* rel  = (const float*)d_in[1];
    const float* mask = (const float*)d_in[2];
    const float* Wih  = (const float*)d_in[3];
    const float* Whh  = (const float*)d_in[4];
    const float* bih  = (const float*)d_in[5];
    const float* bhh  = (const float*)d_in[6];
    const float* w1   = (const float*)d_in[7];
    const float* b1   = (const float*)d_in[8];
    const float* w2   = (const float*)d_in[9];
    const float* b2   = (const float*)d_in[10];
    const float* w3   = (const float*)d_in[11];
    const float* b3   = (const float*)d_in[12];
    const float* w4   = (const float*)d_in[13];
    const float* b4   = (const float*)d_in[14];

    static_assert(SM_TOT * 4 == 106496, "smem layout");
    cudaFuncSetAttribute(k1_lstm_rel, cudaFuncAttributeMaxDynamicSharedMemorySize,
                         SM_TOT * (int)sizeof(float));

    k1_lstm_rel<<<K1_BLOCKS, K1_THREADS, SM_TOT * sizeof(float)>>>(
        x, rel, mask, Wih, Whh, bih, bhh, w1, b1);
    k2_rowexp<<<NN / 256, 256>>>(w2, b2, w3, b3);
    k2b_colsum<<<dim3(NN / 256, 16), 256>>>();
    k2c_invz<<<NN / 256, 256>>>();
    k4_prop<<<dim3(NN / 128, NN / 128), 128>>>();
    k5_final<<<NN / 256, 256>>>(w4, b4, (float*)d_out);
}